// round 1
// baseline (speedup 1.0000x reference)
#include <cuda_runtime.h>

#define BB 4
#define HH 8
#define LQ 256
#define LK 256
#define DKD 64
#define BHN (BB*HH)               // 32
#define NQROWS (BHN*LQ)           // 8192
#define OUT_ELEMS (NQROWS*DKD)    // 524288
#define ATTN_ELEMS (BHN*LQ*LK)    // 2097152

// Scratch (no cudaMalloc allowed)
__device__ float g_qp[NQROWS * DKD];          // [bh*Lq + q][d]
__device__ float g_kpT[BHN * DKD * LK];       // [bh][d][k]  (transposed for conflict-free SMEM)

__device__ __forceinline__ float tanh_fast(float x) {
    float y;
    asm("tanh.approx.f32 %0, %1;" : "=f"(y) : "f"(x));
    return y;
}

// ---------------------------------------------------------------------------
// Kernel 1: projection  out[row][e] = sum_d x[row][d] * W[e][d] + b[e]
// TRANS=false -> write g_qp row-major; TRANS=true -> write g_kpT transposed.
// Block: 256 threads handles 32 rows. Grid: 8192/32 = 256 blocks.
// ---------------------------------------------------------------------------
template <bool TRANS>
__global__ void proj_kernel(const float* __restrict__ x,
                            const float* __restrict__ W,
                            const float* __restrict__ bias)
{
    __shared__ float Ws[DKD][DKD + 1];   // padded: bank = (e + d) % 32, conflict-free
    __shared__ float xs[32][DKD];

    const int tid  = threadIdx.x;        // 0..255
    const int row0 = blockIdx.x * 32;

    for (int i = tid; i < DKD * DKD; i += 256)
        Ws[i >> 6][i & 63] = W[i];
    for (int i = tid; i < 32 * DKD; i += 256)
        xs[i >> 6][i & 63] = x[row0 * DKD + i];
    __syncthreads();

    const int e  = tid & 63;
    const int rg = tid >> 6;             // 0..3 -> rows rg*8 .. rg*8+7
    const float b = bias[e];

    float acc[8];
#pragma unroll
    for (int j = 0; j < 8; j++) acc[j] = 0.f;

#pragma unroll
    for (int d = 0; d < DKD; d++) {
        const float w = Ws[e][d];
#pragma unroll
        for (int j = 0; j < 8; j++)
            acc[j] += w * xs[rg * 8 + j][d];
    }

    if (!TRANS) {
#pragma unroll
        for (int j = 0; j < 8; j++)
            g_qp[(row0 + rg * 8 + j) * DKD + e] = acc[j] + b;
    } else {
        const int bh = row0 / LK;
        const int k0 = row0 % LK;
#pragma unroll
        for (int j = 0; j < 8; j++)
            g_kpT[bh * (DKD * LK) + e * LK + (k0 + rg * 8 + j)] = acc[j] + b;
    }
}

// ---------------------------------------------------------------------------
// Kernel 2: scores + softmax -> attn (written directly into d_out slice)
// scores[q][k] = sum_d vs_w[d] * tanh(qp[q][d] + kp[k][d])   (vs_b dropped:
// softmax is shift-invariant and scores are not an output)
// Grid: 32 bh * 16 q-tiles = 512 CTAs. Block: 128 threads (4 warps).
// Warp handles 4 q rows; lane owns k = ci*32 + lane, ci = 0..7.
// ---------------------------------------------------------------------------
__global__ void attn_scores_kernel(const float* __restrict__ vs_w,
                                   float* __restrict__ attn_out)
{
    __shared__ float kps[DKD][64];       // chunk of 64 k, [d][kc]: bank = kc%32, conflict-free
    __shared__ float qs[16][DKD];
    __shared__ float vsw_s[DKD];

    const int tid  = threadIdx.x;        // 0..127
    const int lane = tid & 31;
    const int warp = tid >> 5;           // 0..3
    const int bh   = blockIdx.x >> 4;
    const int q0   = (blockIdx.x & 15) * 16;

    if (tid < DKD) vsw_s[tid] = vs_w[tid];
    // qs: 16*64 floats = 256 float4, 2 per thread
    {
        const float4* qsrc = (const float4*)(g_qp + (bh * LQ + q0) * DKD);
        float4* qdst = (float4*)&qs[0][0];
        qdst[tid]       = qsrc[tid];
        qdst[tid + 128] = qsrc[tid + 128];
    }
    __syncthreads();

    float sc[4][8];
#pragma unroll
    for (int j = 0; j < 4; j++)
#pragma unroll
        for (int i = 0; i < 8; i++) sc[j][i] = 0.f;

    const int qw = warp * 4;             // warp's q rows within tile

    for (int c = 0; c < 4; c++) {        // k chunks of 64
        __syncthreads();                 // protect previous chunk's readers
        {
            const float* src = g_kpT + bh * (DKD * LK) + c * 64;
            float4* kdst = (float4*)&kps[0][0];
#pragma unroll
            for (int t = 0; t < 8; t++) {
                const int fi  = tid + t * 128;     // float4 index 0..1023
                const int d   = fi >> 4;           // 16 float4 per 64-float row
                const int kc4 = fi & 15;
                kdst[fi] = *(const float4*)(src + d * LK + kc4 * 4);
            }
        }
        __syncthreads();

#pragma unroll
        for (int sub = 0; sub < 2; sub++) {
            const int kc = sub * 32 + lane;
            float a0 = 0.f, a1 = 0.f, a2 = 0.f, a3 = 0.f;
#pragma unroll
            for (int d = 0; d < DKD; d++) {
                const float kv = kps[d][kc];
                const float w  = vsw_s[d];
                a0 += w * tanh_fast(qs[qw + 0][d] + kv);
                a1 += w * tanh_fast(qs[qw + 1][d] + kv);
                a2 += w * tanh_fast(qs[qw + 2][d] + kv);
                a3 += w * tanh_fast(qs[qw + 3][d] + kv);
            }
            const int ci = c * 2 + sub;
            sc[0][ci] = a0; sc[1][ci] = a1; sc[2][ci] = a2; sc[3][ci] = a3;
        }
    }

    // softmax per q row (256 values spread across warp, 8 per lane)
#pragma unroll
    for (int j = 0; j < 4; j++) {
        float m = sc[j][0];
#pragma unroll
        for (int i = 1; i < 8; i++) m = fmaxf(m, sc[j][i]);
#pragma unroll
        for (int o = 16; o > 0; o >>= 1)
            m = fmaxf(m, __shfl_xor_sync(0xffffffffu, m, o));

        float p[8];
        float s = 0.f;
#pragma unroll
        for (int i = 0; i < 8; i++) { p[i] = __expf(sc[j][i] - m); s += p[i]; }
#pragma unroll
        for (int o = 16; o > 0; o >>= 1)
            s += __shfl_xor_sync(0xffffffffu, s, o);

        const float inv = 1.0f / s;
        const int q = q0 + qw + j;
        float* dst = attn_out + (bh * LQ + q) * LK;
#pragma unroll
        for (int i = 0; i < 8; i++)
            dst[i * 32 + lane] = p[i] * inv;
    }
}

// ---------------------------------------------------------------------------
// Kernel 3: output = attn @ v.  Grid: 32 bh * 8 = 256 CTAs, 256 threads.
// Warp = 4 q rows, lane = 2 d's (float2). attn loads are warp-uniform.
// ---------------------------------------------------------------------------
__global__ void out_gemm_kernel(const float* __restrict__ v,
                                const float* __restrict__ attn,
                                float* __restrict__ out)
{
    const int tid  = threadIdx.x;
    const int lane = tid & 31;
    const int warp = tid >> 5;           // 0..7
    const int bh   = blockIdx.x >> 3;
    const int q0   = (blockIdx.x & 7) * 32 + warp * 4;

    const float2* vv = (const float2*)(v + bh * LK * DKD);
    const float* ar  = attn + (bh * LQ + q0) * LK;

    float2 acc0 = make_float2(0.f, 0.f), acc1 = acc0, acc2 = acc0, acc3 = acc0;

#pragma unroll 4
    for (int k = 0; k < LK; k++) {
        const float2 vk = vv[k * 32 + lane];
        const float a0 = ar[k];
        const float a1 = ar[LK + k];
        const float a2 = ar[2 * LK + k];
        const float a3 = ar[3 * LK + k];
        acc0.x += a0 * vk.x; acc0.y += a0 * vk.y;
        acc1.x += a1 * vk.x; acc1.y += a1 * vk.y;
        acc2.x += a2 * vk.x; acc2.y += a2 * vk.y;
        acc3.x += a3 * vk.x; acc3.y += a3 * vk.y;
    }

    float2* od = (float2*)(out + (bh * LQ + q0) * DKD);
    od[lane]      = acc0;
    od[32 + lane] = acc1;
    od[64 + lane] = acc2;
    od[96 + lane] = acc3;
}

// ---------------------------------------------------------------------------
extern "C" void kernel_launch(void* const* d_in, const int* in_sizes, int n_in,
                              void* d_out, int out_size)
{
    (void)in_sizes; (void)n_in; (void)out_size;
    const float* q    = (const float*)d_in[0];
    const float* k    = (const float*)d_in[1];
    const float* v    = (const float*)d_in[2];
    const float* Wq_w = (const float*)d_in[3];
    const float* Wq_b = (const float*)d_in[4];
    const float* Wk_w = (const float*)d_in[5];
    const float* Wk_b = (const float*)d_in[6];
    const float* vs_w = (const float*)d_in[7];
    // d_in[8] = vs_b: unused (softmax shift-invariance; scores not an output)

    float* out  = (float*)d_out;            // [B,H,Lq,Dk]
    float* attn = out + OUT_ELEMS;          // [B,H,Lq,Lk]

    proj_kernel<false><<<NQROWS / 32, 256>>>(q, Wq_w, Wq_b);
    proj_kernel<true><<<NQROWS / 32, 256>>>(k, Wk_w, Wk_b);
    attn_scores_kernel<<<BHN * (LQ / 16), 128>>>(vs_w, attn);
    out_gemm_kernel<<<BHN * (LQ / 32), 256>>>(v, attn, out);
}

// round 2
// speedup vs baseline: 1.3383x; 1.3383x over previous
#include <cuda_runtime.h>

#define BB 4
#define HH 8
#define LQ 256
#define LK 256
#define DKD 64
#define BHN (BB*HH)               // 32
#define NQROWS (BHN*LQ)           // 8192
#define OUT_ELEMS (NQROWS*DKD)    // 524288

// Scratch (no cudaMalloc allowed)
__device__ float g_qp[NQROWS * DKD];          // [bh*Lq + q][d]
__device__ float g_kpT[BHN * DKD * LK];       // [bh][d][k]  (transposed for conflict-free SMEM)

__device__ __forceinline__ float tanh_fast(float x) {
    float y;
    asm("tanh.approx.f32 %0, %1;" : "=f"(y) : "f"(x));
    return y;
}

// ---------------------------------------------------------------------------
// Kernel 1: both projections in one launch.
// blocks [0,256): qp rows (row-major). blocks [256,512): kp rows (transposed).
// Block: 256 threads handles 32 rows.
// ---------------------------------------------------------------------------
__global__ void proj_kernel(const float* __restrict__ xq,
                            const float* __restrict__ xk,
                            const float* __restrict__ Wq,
                            const float* __restrict__ bq,
                            const float* __restrict__ Wk,
                            const float* __restrict__ bk)
{
    __shared__ float Ws[DKD][DKD + 1];   // padded: conflict-free
    __shared__ float xs[32][DKD];

    const bool is_k = blockIdx.x >= 256;
    const int  blk  = is_k ? (blockIdx.x - 256) : blockIdx.x;
    const float* x  = is_k ? xk : xq;
    const float* W  = is_k ? Wk : Wq;
    const float* bi = is_k ? bk : bq;

    const int tid  = threadIdx.x;        // 0..255
    const int row0 = blk * 32;

    for (int i = tid; i < DKD * DKD; i += 256)
        Ws[i >> 6][i & 63] = W[i];
    for (int i = tid; i < 32 * DKD; i += 256)
        xs[i >> 6][i & 63] = x[row0 * DKD + i];
    __syncthreads();

    const int e  = tid & 63;
    const int rg = tid >> 6;             // 0..3 -> rows rg*8 .. rg*8+7
    const float b = bi[e];

    float acc[8];
#pragma unroll
    for (int j = 0; j < 8; j++) acc[j] = 0.f;

#pragma unroll
    for (int d = 0; d < DKD; d++) {
        const float w = Ws[e][d];
#pragma unroll
        for (int j = 0; j < 8; j++)
            acc[j] += w * xs[rg * 8 + j][d];
    }

    if (!is_k) {
#pragma unroll
        for (int j = 0; j < 8; j++)
            g_qp[(row0 + rg * 8 + j) * DKD + e] = acc[j] + b;
    } else {
        const int bh = row0 / LK;
        const int k0 = row0 % LK;
#pragma unroll
        for (int j = 0; j < 8; j++)
            g_kpT[bh * (DKD * LK) + e * LK + (k0 + rg * 8 + j)] = acc[j] + b;
    }
}

// ---------------------------------------------------------------------------
// Kernel 2 (fused): scores + softmax -> attn (global) AND output = attn @ v.
// Grid: 32 bh * 16 q-tiles = 512 CTAs. Block: 128 threads (4 warps).
// Phase 1: warp handles 4 q rows; lane owns k = i*32 + lane, i = 0..7.
//          vs_b dropped (softmax shift-invariant; raw scores not an output).
// Phase 2: p kept in SMEM; v streamed through the same 16KB staging buffer.
//          thread (q = tid&15, dg = tid>>4) accumulates out[q][dg*8..dg*8+7].
// ---------------------------------------------------------------------------
__global__ void attn_fused_kernel(const float* __restrict__ vs_w,
                                  const float* __restrict__ v,
                                  float* __restrict__ out,
                                  float* __restrict__ attn_out)
{
    __shared__ float kv[DKD * 64];       // phase1: kp chunk [d][kc]; phase2: v chunk [kk][d]
    __shared__ float qs[16][DKD];
    __shared__ float p_s[16][LK + 1];    // padded: row stride 257 -> bank (q+k)%32
    __shared__ float vsw_s[DKD];

    const int tid  = threadIdx.x;        // 0..127
    const int lane = tid & 31;
    const int warp = tid >> 5;           // 0..3
    const int bh   = blockIdx.x >> 4;
    const int q0   = (blockIdx.x & 15) * 16;

    if (tid < DKD) vsw_s[tid] = vs_w[tid];
    {
        const float4* qsrc = (const float4*)(g_qp + (bh * LQ + q0) * DKD);
        float4* qdst = (float4*)&qs[0][0];
        qdst[tid]       = qsrc[tid];
        qdst[tid + 128] = qsrc[tid + 128];
    }
    __syncthreads();

    float sc[4][8];
#pragma unroll
    for (int j = 0; j < 4; j++)
#pragma unroll
        for (int i = 0; i < 8; i++) sc[j][i] = 0.f;

    const int qw = warp * 4;             // warp's q rows within tile

    // ---- Phase 1: scores ----
    for (int c = 0; c < 4; c++) {        // k chunks of 64
        if (c) __syncthreads();          // protect previous chunk's readers
        {
            const float* src = g_kpT + bh * (DKD * LK) + c * 64;
            float4* kdst = (float4*)&kv[0];
#pragma unroll
            for (int t = 0; t < 8; t++) {
                const int fi  = tid + t * 128;     // float4 index 0..1023
                const int d   = fi >> 4;           // 16 float4 per 64-float row
                const int kc4 = fi & 15;
                kdst[fi] = *(const float4*)(src + d * LK + kc4 * 4);
            }
        }
        __syncthreads();

#pragma unroll
        for (int sub = 0; sub < 2; sub++) {
            const int kc = sub * 32 + lane;
            float a0 = 0.f, a1 = 0.f, a2 = 0.f, a3 = 0.f;
#pragma unroll
            for (int d = 0; d < DKD; d++) {
                const float kvv = kv[d * 64 + kc];
                const float w   = vsw_s[d];
                a0 += w * tanh_fast(qs[qw + 0][d] + kvv);
                a1 += w * tanh_fast(qs[qw + 1][d] + kvv);
                a2 += w * tanh_fast(qs[qw + 2][d] + kvv);
                a3 += w * tanh_fast(qs[qw + 3][d] + kvv);
            }
            const int ci = c * 2 + sub;
            sc[0][ci] = a0; sc[1][ci] = a1; sc[2][ci] = a2; sc[3][ci] = a3;
        }
    }

    // ---- softmax per q row; write attn to global AND to p_s ----
#pragma unroll
    for (int j = 0; j < 4; j++) {
        float m = sc[j][0];
#pragma unroll
        for (int i = 1; i < 8; i++) m = fmaxf(m, sc[j][i]);
#pragma unroll
        for (int o = 16; o > 0; o >>= 1)
            m = fmaxf(m, __shfl_xor_sync(0xffffffffu, m, o));

        float p[8];
        float s = 0.f;
#pragma unroll
        for (int i = 0; i < 8; i++) { p[i] = __expf(sc[j][i] - m); s += p[i]; }
#pragma unroll
        for (int o = 16; o > 0; o >>= 1)
            s += __shfl_xor_sync(0xffffffffu, s, o);

        const float inv = 1.0f / s;
        const int qr = qw + j;
        float* dst = attn_out + (bh * LQ + q0 + qr) * LK;
#pragma unroll
        for (int i = 0; i < 8; i++) {
            const float pv = p[i] * inv;
            dst[i * 32 + lane]         = pv;
            p_s[qr][i * 32 + lane]     = pv;
        }
    }
    __syncthreads();

    // ---- Phase 2: out[q][d] = sum_k p[q][k] * v[k][d] ----
    const int q  = tid & 15;             // output q row within tile
    const int dg = tid >> 4;             // 0..7 -> d = dg*8 .. dg*8+7

    float acc[8];
#pragma unroll
    for (int i = 0; i < 8; i++) acc[i] = 0.f;

    for (int c = 0; c < 4; c++) {        // v chunks of 64 k-rows
        if (c) __syncthreads();
        {
            const float4* src = (const float4*)(v + bh * LK * DKD + c * 64 * DKD);
            float4* vdst = (float4*)&kv[0];
#pragma unroll
            for (int t = 0; t < 8; t++)
                vdst[tid + t * 128] = src[tid + t * 128];
        }
        __syncthreads();

#pragma unroll 4
        for (int kk = 0; kk < 64; kk++) {
            const float a  = p_s[q][c * 64 + kk];
            const float4 v0 = *(const float4*)&kv[kk * 64 + dg * 8];
            const float4 v1 = *(const float4*)&kv[kk * 64 + dg * 8 + 4];
            acc[0] += a * v0.x; acc[1] += a * v0.y;
            acc[2] += a * v0.z; acc[3] += a * v0.w;
            acc[4] += a * v1.x; acc[5] += a * v1.y;
            acc[6] += a * v1.z; acc[7] += a * v1.w;
        }
    }

    float* od = out + (bh * LQ + q0 + q) * DKD + dg * 8;
    *(float4*)od       = make_float4(acc[0], acc[1], acc[2], acc[3]);
    *(float4*)(od + 4) = make_float4(acc[4], acc[5], acc[6], acc[7]);
}

// ---------------------------------------------------------------------------
extern "C" void kernel_launch(void* const* d_in, const int* in_sizes, int n_in,
                              void* d_out, int out_size)
{
    (void)in_sizes; (void)n_in; (void)out_size;
    const float* q    = (const float*)d_in[0];
    const float* k    = (const float*)d_in[1];
    const float* v    = (const float*)d_in[2];
    const float* Wq_w = (const float*)d_in[3];
    const float* Wq_b = (const float*)d_in[4];
    const float* Wk_w = (const float*)d_in[5];
    const float* Wk_b = (const float*)d_in[6];
    const float* vs_w = (const float*)d_in[7];
    // d_in[8] = vs_b: unused (softmax shift-invariance; scores not an output)

    float* out  = (float*)d_out;            // [B,H,Lq,Dk]
    float* attn = out + OUT_ELEMS;          // [B,H,Lq,Lk]

    proj_kernel<<<512, 256>>>(q, k, Wq_w, Wq_b, Wk_w, Wk_b);
    attn_fused_kernel<<<BHN * (LQ / 16), 128>>>(vs_w, v, out, attn);
}

// round 3
// speedup vs baseline: 1.5195x; 1.1354x over previous
#include <cuda_runtime.h>

#define BB 4
#define HH 8
#define LQ 256
#define LK 256
#define DKD 64
#define BHN (BB*HH)               // 32
#define NQROWS (BHN*LQ)           // 8192
#define OUT_ELEMS (NQROWS*DKD)    // 524288

#define KVSTRIDE 66               // padded SMEM row stride for [k][d] chunks

// Scratch (no cudaMalloc allowed) — both row-major now
__device__ float g_qp[NQROWS * DKD];          // [bh*Lq + q][d]
__device__ float g_kp[NQROWS * DKD];          // [bh*Lk + k][d]

__device__ __forceinline__ float tanh_fast(float x) {
    float y;
    asm("tanh.approx.f32 %0, %1;" : "=f"(y) : "f"(x));
    return y;
}

// ---------------------------------------------------------------------------
// Kernel 1: both projections in one launch, both outputs row-major (coalesced).
// blocks [0,256): qp rows. blocks [256,512): kp rows.
// Block: 256 threads handles 32 rows.
// ---------------------------------------------------------------------------
__global__ void proj_kernel(const float* __restrict__ xq,
                            const float* __restrict__ xk,
                            const float* __restrict__ Wq,
                            const float* __restrict__ bq,
                            const float* __restrict__ Wk,
                            const float* __restrict__ bk)
{
    __shared__ float Ws[DKD][DKD + 1];   // padded: conflict-free
    __shared__ float xs[32][DKD];

    const bool is_k = blockIdx.x >= 256;
    const int  blk  = is_k ? (blockIdx.x - 256) : blockIdx.x;
    const float* x  = is_k ? xk : xq;
    const float* W  = is_k ? Wk : Wq;
    const float* bi = is_k ? bk : bq;
    float* dst      = is_k ? g_kp : g_qp;

    const int tid  = threadIdx.x;        // 0..255
    const int row0 = blk * 32;

    for (int i = tid; i < DKD * DKD; i += 256)
        Ws[i >> 6][i & 63] = W[i];
    for (int i = tid; i < 32 * DKD; i += 256)
        xs[i >> 6][i & 63] = x[row0 * DKD + i];
    __syncthreads();

    const int e  = tid & 63;
    const int rg = tid >> 6;             // 0..3 -> rows rg*8 .. rg*8+7
    const float b = bi[e];

    float acc[8];
#pragma unroll
    for (int j = 0; j < 8; j++) acc[j] = 0.f;

#pragma unroll
    for (int d = 0; d < DKD; d++) {
        const float w = Ws[e][d];
#pragma unroll
        for (int j = 0; j < 8; j++)
            acc[j] += w * xs[rg * 8 + j][d];
    }

#pragma unroll
    for (int j = 0; j < 8; j++)
        dst[(row0 + rg * 8 + j) * DKD + e] = acc[j] + b;   // coalesced
}

// ---------------------------------------------------------------------------
// Kernel 2 (fused): scores + softmax -> attn AND output = attn @ v.
// Grid: 32 bh * 32 q-tiles = 1024 CTAs (single balanced wave, ~7 CTAs/SM).
// Block: 128 threads (4 warps); warp handles 2 q rows.
// kp/v chunks staged in SMEM as [k][d] with padded stride 66:
//   phase-1 read kv[kc*66+d] -> bank (2kc+d)%32, 2-way conflict max.
//   phase-2 read kv[kk*66+d] -> few-address broadcast.
// vs_b dropped (softmax shift-invariant; raw scores not an output).
// ---------------------------------------------------------------------------
__global__ void __launch_bounds__(128, 7)
attn_fused_kernel(const float* __restrict__ vs_w,
                  const float* __restrict__ v,
                  float* __restrict__ out,
                  float* __restrict__ attn_out)
{
    __shared__ float kv[64 * KVSTRIDE];  // 64 k-rows x 64 d (padded)
    __shared__ float qs[8][DKD];
    __shared__ float p_s[8][LK + 1];     // stride 257: bank (q+k)%32
    __shared__ float vsw_s[DKD];

    const int tid  = threadIdx.x;        // 0..127
    const int lane = tid & 31;
    const int warp = tid >> 5;           // 0..3
    const int bh   = blockIdx.x >> 5;
    const int q0   = (blockIdx.x & 31) * 8;

    if (tid < DKD) vsw_s[tid] = vs_w[tid];
    {   // qs: 8*64 floats = 128 float4, one per thread
        const float4* qsrc = (const float4*)(g_qp + (bh * LQ + q0) * DKD);
        ((float4*)&qs[0][0])[tid] = qsrc[tid];
    }
    __syncthreads();

    float sc[2][8];
#pragma unroll
    for (int j = 0; j < 2; j++)
#pragma unroll
        for (int i = 0; i < 8; i++) sc[j][i] = 0.f;

    const int qw = warp * 2;             // warp's q rows within tile

    // ---- Phase 1: scores ----
    for (int c = 0; c < 4; c++) {        // k chunks of 64 rows
        if (c) __syncthreads();
        {   // coalesced copy g_kp chunk -> padded SMEM [k][d]
            const float2* src = (const float2*)(g_kp + (bh * LK + c * 64) * DKD);
#pragma unroll
            for (int t = 0; t < 16; t++) {
                const int f  = tid + t * 128;      // float2 index 0..2047
                const int k  = f >> 5;             // 32 float2 per row
                const int d2 = f & 31;
                *(float2*)&kv[k * KVSTRIDE + 2 * d2] = src[f];
            }
        }
        __syncthreads();

#pragma unroll
        for (int sub = 0; sub < 2; sub++) {
            const int kc = sub * 32 + lane;
            const float* krow = &kv[kc * KVSTRIDE];
            float a0 = 0.f, a1 = 0.f;
#pragma unroll
            for (int d = 0; d < DKD; d++) {
                const float kvv = krow[d];
                const float w   = vsw_s[d];
                a0 += w * tanh_fast(qs[qw + 0][d] + kvv);
                a1 += w * tanh_fast(qs[qw + 1][d] + kvv);
            }
            sc[0][c * 2 + sub] = a0;
            sc[1][c * 2 + sub] = a1;
        }
    }

    // ---- softmax per q row; write attn to global AND to p_s ----
#pragma unroll
    for (int j = 0; j < 2; j++) {
        float m = sc[j][0];
#pragma unroll
        for (int i = 1; i < 8; i++) m = fmaxf(m, sc[j][i]);
#pragma unroll
        for (int o = 16; o > 0; o >>= 1)
            m = fmaxf(m, __shfl_xor_sync(0xffffffffu, m, o));

        float p[8];
        float s = 0.f;
#pragma unroll
        for (int i = 0; i < 8; i++) { p[i] = __expf(sc[j][i] - m); s += p[i]; }
#pragma unroll
        for (int o = 16; o > 0; o >>= 1)
            s += __shfl_xor_sync(0xffffffffu, s, o);

        const float inv = 1.0f / s;
        const int qr = qw + j;
        float* dst = attn_out + (bh * LQ + q0 + qr) * LK;
#pragma unroll
        for (int i = 0; i < 8; i++) {
            const float pv = p[i] * inv;
            dst[i * 32 + lane]     = pv;
            p_s[qr][i * 32 + lane] = pv;
        }
    }
    __syncthreads();

    // ---- Phase 2: out[q][d] = sum_k p[q][k] * v[k][d] ----
    const int q  = tid & 7;              // output q row within tile
    const int dg = tid >> 3;             // 0..15 -> d = dg*4 .. dg*4+3

    float acc[4];
#pragma unroll
    for (int i = 0; i < 4; i++) acc[i] = 0.f;

    for (int c = 0; c < 4; c++) {        // v chunks of 64 k-rows
        __syncthreads();                 // kv free (phase1 chunk or prev v chunk)
        {
            const float2* src = (const float2*)(v + (bh * LK + c * 64) * DKD);
#pragma unroll
            for (int t = 0; t < 16; t++) {
                const int f  = tid + t * 128;
                const int k  = f >> 5;
                const int d2 = f & 31;
                *(float2*)&kv[k * KVSTRIDE + 2 * d2] = src[f];
            }
        }
        __syncthreads();

#pragma unroll 4
        for (int kk = 0; kk < 64; kk++) {
            const float a  = p_s[q][c * 64 + kk];
            const float2 v0 = *(const float2*)&kv[kk * KVSTRIDE + dg * 4];
            const float2 v1 = *(const float2*)&kv[kk * KVSTRIDE + dg * 4 + 2];
            acc[0] += a * v0.x; acc[1] += a * v0.y;
            acc[2] += a * v1.x; acc[3] += a * v1.y;
        }
    }

    float* od = out + (bh * LQ + q0 + q) * DKD + dg * 4;
    *(float4*)od = make_float4(acc[0], acc[1], acc[2], acc[3]);
}

// ---------------------------------------------------------------------------
extern "C" void kernel_launch(void* const* d_in, const int* in_sizes, int n_in,
                              void* d_out, int out_size)
{
    (void)in_sizes; (void)n_in; (void)out_size;
    const float* q    = (const float*)d_in[0];
    const float* k    = (const float*)d_in[1];
    const float* v    = (const float*)d_in[2];
    const float* Wq_w = (const float*)d_in[3];
    const float* Wq_b = (const float*)d_in[4];
    const float* Wk_w = (const float*)d_in[5];
    const float* Wk_b = (const float*)d_in[6];
    const float* vs_w = (const float*)d_in[7];
    // d_in[8] = vs_b: unused (softmax shift-invariance; scores not an output)

    float* out  = (float*)d_out;            // [B,H,Lq,Dk]
    float* attn = out + OUT_ELEMS;          // [B,H,Lq,Lk]

    proj_kernel<<<512, 256>>>(q, k, Wq_w, Wq_b, Wk_w, Wk_b);
    attn_fused_kernel<<<BHN * (LQ / 8), 128>>>(vs_w, v, out, attn);
}

// round 4
// speedup vs baseline: 1.5254x; 1.0039x over previous
#include <cuda_runtime.h>

#define BB 4
#define HH 8
#define LQ 256
#define LK 256
#define DKD 64
#define BHN (BB*HH)               // 32
#define NQROWS (BHN*LQ)           // 8192
#define OUT_ELEMS (NQROWS*DKD)    // 524288

#define VSTRIDE 66                // phase-2 SMEM [k][d] stride
#define PSTRIDE 258               // p_s row stride (even -> aligned float2, conflict-free)

// Scratch (no cudaMalloc allowed)
__device__ float g_qp[NQROWS * DKD];          // [bh*Lq + q][d]
__device__ float g_kpT[BHN * DKD * LK];       // [bh][d][k]  (k-contiguous)

__device__ __forceinline__ float tanh_fast(float x) {
    float y;
    asm("tanh.approx.f32 %0, %1;" : "=f"(y) : "f"(x));
    return y;
}

// ---------------------------------------------------------------------------
// Kernel 1: both projections. blocks [0,128): qp rows. [128,256): kp rows.
// 512 threads / 64 rows per block (halves W reloads vs 32-row blocks).
// q path: row-major coalesced. k path: transposed [d][k], 2x STG.128/thread.
// ---------------------------------------------------------------------------
__global__ void proj_kernel(const float* __restrict__ xq,
                            const float* __restrict__ xk,
                            const float* __restrict__ Wq,
                            const float* __restrict__ bq,
                            const float* __restrict__ Wk,
                            const float* __restrict__ bk)
{
    __shared__ float Ws[DKD][DKD + 1];
    __shared__ float xs[64][DKD];

    const bool is_k = blockIdx.x >= 128;
    const int  blk  = is_k ? (blockIdx.x - 128) : blockIdx.x;
    const float* x  = is_k ? xk : xq;
    const float* W  = is_k ? Wk : Wq;
    const float* bi = is_k ? bk : bq;

    const int tid  = threadIdx.x;        // 0..511
    const int row0 = blk * 64;

    for (int i = tid; i < DKD * DKD; i += 512)
        Ws[i >> 6][i & 63] = W[i];
    for (int i = tid; i < 64 * DKD; i += 512)
        xs[i >> 6][i & 63] = x[row0 * DKD + i];
    __syncthreads();

    const int e  = tid & 63;
    const int rg = tid >> 6;             // 0..7 -> rows rg*8 .. rg*8+7
    const float b = bi[e];

    float acc[8];
#pragma unroll
    for (int j = 0; j < 8; j++) acc[j] = 0.f;

#pragma unroll
    for (int d = 0; d < DKD; d++) {
        const float w = Ws[e][d];
#pragma unroll
        for (int j = 0; j < 8; j++)
            acc[j] += w * xs[rg * 8 + j][d];
    }

    if (!is_k) {
#pragma unroll
        for (int j = 0; j < 8; j++)
            g_qp[(row0 + rg * 8 + j) * DKD + e] = acc[j] + b;   // coalesced
    } else {
        const int bh = row0 >> 8;
        const int k0 = (row0 & 255) + rg * 8;
        float* dst = g_kpT + bh * (DKD * LK) + e * LK + k0;     // 8 consecutive k
        *(float4*)dst       = make_float4(acc[0]+b, acc[1]+b, acc[2]+b, acc[3]+b);
        *(float4*)(dst + 4) = make_float4(acc[4]+b, acc[5]+b, acc[6]+b, acc[7]+b);
    }
}

// ---------------------------------------------------------------------------
// Kernel 2 (fused): scores + softmax -> attn AND output = attn @ v.
// Grid: 32 bh * 32 q-tiles = 1024 CTAs. Block: 128 threads (4 warps).
// Phase 1: warp = 2 q rows; lane = k-pair {2*lane, 2*lane+1}; one pass per
//   64-k chunk. kp staged [d][64k] stride 64 (conflict-free LDS.64);
//   q staged transposed qsT[d][8] (8B broadcast). 15 issues / 4 MUFU.
// Phase 2: p in p_s (stride 258); v staged [k][d] stride 66.
// vs_b dropped (softmax shift-invariant; raw scores not an output).
// ---------------------------------------------------------------------------
__global__ void __launch_bounds__(128, 7)
attn_fused_kernel(const float* __restrict__ vs_w,
                  const float* __restrict__ v,
                  float* __restrict__ out,
                  float* __restrict__ attn_out)
{
    __shared__ float kv[64 * VSTRIDE];   // phase1 uses [d][64] (4096); phase2 [k][66]
    __shared__ float qsT[DKD * 8];       // [d][qr]
    __shared__ float p_s[8 * PSTRIDE];   // [qr][k] padded
    __shared__ float vsw_s[DKD];

    const int tid  = threadIdx.x;        // 0..127
    const int lane = tid & 31;
    const int warp = tid >> 5;           // 0..3
    const int bh   = blockIdx.x >> 5;
    const int q0   = (blockIdx.x & 31) * 8;

    if (tid < DKD) vsw_s[tid] = vs_w[tid];
    {   // load 8 q rows, transpose to qsT[d][qr]
        const int qr = tid & 7;
        const int d4 = tid >> 3;         // 0..15
        const float4 qv = *(const float4*)(g_qp + (bh * LQ + q0 + qr) * DKD + d4 * 4);
        qsT[(d4 * 4 + 0) * 8 + qr] = qv.x;
        qsT[(d4 * 4 + 1) * 8 + qr] = qv.y;
        qsT[(d4 * 4 + 2) * 8 + qr] = qv.z;
        qsT[(d4 * 4 + 3) * 8 + qr] = qv.w;
    }
    __syncthreads();

    float sc[2][8];
#pragma unroll
    for (int j = 0; j < 2; j++)
#pragma unroll
        for (int i = 0; i < 8; i++) sc[j][i] = 0.f;

    const int qw = warp * 2;             // warp's q rows within tile
    const int k2 = lane * 2;             // lane's k-pair within chunk

    // ---- Phase 1: scores ----
    for (int c = 0; c < 4; c++) {        // k chunks of 64
        if (c) __syncthreads();
        {   // stage g_kpT chunk -> kv[d][kc] (straight coalesced float4 copy)
            const float4* src = (const float4*)(g_kpT + bh * (DKD * LK) + c * 64);
            float4* dst = (float4*)kv;
#pragma unroll
            for (int t = 0; t < 8; t++) {
                const int f4  = tid + t * 128;     // 0..1023
                const int d   = f4 >> 4;
                const int kc4 = f4 & 15;
                dst[f4] = src[d * (LK / 4) + kc4];
            }
        }
        __syncthreads();

        float a00 = 0.f, a01 = 0.f, a10 = 0.f, a11 = 0.f;
#pragma unroll
        for (int d = 0; d < DKD; d++) {
            const float2 kp = *(const float2*)&kv[d * 64 + k2];
            const float2 qp = *(const float2*)&qsT[d * 8 + qw];
            const float w   = vsw_s[d];
            a00 += w * tanh_fast(qp.x + kp.x);
            a01 += w * tanh_fast(qp.x + kp.y);
            a10 += w * tanh_fast(qp.y + kp.x);
            a11 += w * tanh_fast(qp.y + kp.y);
        }
        sc[0][c * 2 + 0] = a00; sc[0][c * 2 + 1] = a01;
        sc[1][c * 2 + 0] = a10; sc[1][c * 2 + 1] = a11;
    }

    // ---- softmax per q row; lane holds k = c*64 + 2*lane + kk ----
#pragma unroll
    for (int j = 0; j < 2; j++) {
        float m = sc[j][0];
#pragma unroll
        for (int i = 1; i < 8; i++) m = fmaxf(m, sc[j][i]);
#pragma unroll
        for (int o = 16; o > 0; o >>= 1)
            m = fmaxf(m, __shfl_xor_sync(0xffffffffu, m, o));

        float p[8];
        float s = 0.f;
#pragma unroll
        for (int i = 0; i < 8; i++) { p[i] = __expf(sc[j][i] - m); s += p[i]; }
#pragma unroll
        for (int o = 16; o > 0; o >>= 1)
            s += __shfl_xor_sync(0xffffffffu, s, o);

        const float inv = 1.0f / s;
        const int qr = qw + j;
        float* dst = attn_out + (bh * LQ + q0 + qr) * LK;
#pragma unroll
        for (int c = 0; c < 4; c++) {
            const float2 pv = make_float2(p[c * 2] * inv, p[c * 2 + 1] * inv);
            *(float2*)&dst[c * 64 + k2]               = pv;
            *(float2*)&p_s[qr * PSTRIDE + c * 64 + k2] = pv;
        }
    }
    __syncthreads();

    // ---- Phase 2: out[q][d] = sum_k p[q][k] * v[k][d] ----
    const int q  = tid & 7;              // output q row within tile
    const int dg = tid >> 3;             // 0..15 -> d = dg*4 .. dg*4+3

    float acc[4];
#pragma unroll
    for (int i = 0; i < 4; i++) acc[i] = 0.f;

    for (int c = 0; c < 4; c++) {        // v chunks of 64 k-rows
        if (c) __syncthreads();
        {
            const float2* src = (const float2*)(v + (bh * LK + c * 64) * DKD);
#pragma unroll
            for (int t = 0; t < 16; t++) {
                const int f  = tid + t * 128;
                const int k  = f >> 5;
                const int d2 = f & 31;
                *(float2*)&kv[k * VSTRIDE + 2 * d2] = src[f];
            }
        }
        __syncthreads();

#pragma unroll 4
        for (int kk = 0; kk < 64; kk++) {
            const float a   = p_s[q * PSTRIDE + c * 64 + kk];
            const float2 v0 = *(const float2*)&kv[kk * VSTRIDE + dg * 4];
            const float2 v1 = *(const float2*)&kv[kk * VSTRIDE + dg * 4 + 2];
            acc[0] += a * v0.x; acc[1] += a * v0.y;
            acc[2] += a * v1.x; acc[3] += a * v1.y;
        }
    }

    float* od = out + (bh * LQ + q0 + q) * DKD + dg * 4;
    *(float4*)od = make_float4(acc[0], acc[1], acc[2], acc[3]);
}

// ---------------------------------------------------------------------------
extern "C" void kernel_launch(void* const* d_in, const int* in_sizes, int n_in,
                              void* d_out, int out_size)
{
    (void)in_sizes; (void)n_in; (void)out_size;
    const float* q    = (const float*)d_in[0];
    const float* k    = (const float*)d_in[1];
    const float* v    = (const float*)d_in[2];
    const float* Wq_w = (const float*)d_in[3];
    const float* Wq_b = (const float*)d_in[4];
    const float* Wk_w = (const float*)d_in[5];
    const float* Wk_b = (const float*)d_in[6];
    const float* vs_w = (const float*)d_in[7];
    // d_in[8] = vs_b: unused (softmax shift-invariance; scores not an output)

    float* out  = (float*)d_out;            // [B,H,Lq,Dk]
    float* attn = out + OUT_ELEMS;          // [B,H,Lq,Lk]

    proj_kernel<<<256, 512>>>(q, k, Wq_w, Wq_b, Wk_w, Wk_b);
    attn_fused_kernel<<<BHN * (LQ / 8), 128>>>(vs_w, v, out, attn);
}

// round 5
// speedup vs baseline: 1.5960x; 1.0462x over previous
#include <cuda_runtime.h>
#include <cuda_fp16.h>
#include <cstdint>

#define BB 4
#define HH 8
#define LQ 256
#define LK 256
#define DKD 64
#define BHN (BB*HH)               // 32
#define NQROWS (BHN*LQ)           // 8192
#define OUT_ELEMS (NQROWS*DKD)    // 524288

#define VSTRIDE 66                // phase-2 SMEM [k][d] stride (floats)
#define PSTRIDE 258               // p_s row stride

// Scratch (no cudaMalloc allowed)
__device__ float    g_qp[NQROWS * DKD];            // [bh*Lq + q][d] f32
__device__ uint32_t g_kph[BHN * DKD * (LK / 2)];   // [bh][d][pair] f16x2 (k-pairs)

__device__ __forceinline__ uint32_t tanh2(uint32_t x) {
    uint32_t y;
    asm("tanh.approx.f16x2 %0, %1;" : "=r"(y) : "r"(x));
    return y;
}
__device__ __forceinline__ uint32_t hadd2u(uint32_t a, uint32_t b) {
    uint32_t d;
    asm("add.f16x2 %0, %1, %2;" : "=r"(d) : "r"(a), "r"(b));
    return d;
}
__device__ __forceinline__ uint32_t hfma2u(uint32_t a, uint32_t b, uint32_t c) {
    uint32_t d;
    asm("fma.rn.f16x2 %0, %1, %2, %3;" : "=r"(d) : "r"(a), "r"(b), "r"(c));
    return d;
}
__device__ __forceinline__ uint32_t pack2(float lo, float hi) {   // low half = lo
    __half2 h = __floats2half2_rn(lo, hi);
    return *reinterpret_cast<uint32_t*>(&h);
}
__device__ __forceinline__ uint32_t dup2(float x) {
    return pack2(x, x);
}
__device__ __forceinline__ float2 unpack2(uint32_t v) {           // .x = low half
    __half2 h = *reinterpret_cast<__half2*>(&v);
    return __half22float2(h);
}

// ---------------------------------------------------------------------------
// Kernel 1: both projections. blocks [0,128): qp rows (f32 row-major).
// [128,256): kp rows -> g_kph packed f16x2 k-pairs, [bh][d][pair].
// 512 threads / 64 rows per block.
// ---------------------------------------------------------------------------
__global__ void proj_kernel(const float* __restrict__ xq,
                            const float* __restrict__ xk,
                            const float* __restrict__ Wq,
                            const float* __restrict__ bq,
                            const float* __restrict__ Wk,
                            const float* __restrict__ bk)
{
    __shared__ float Ws[DKD][DKD + 1];
    __shared__ float xs[64][DKD];

    const bool is_k = blockIdx.x >= 128;
    const int  blk  = is_k ? (blockIdx.x - 128) : blockIdx.x;
    const float* x  = is_k ? xk : xq;
    const float* W  = is_k ? Wk : Wq;
    const float* bi = is_k ? bk : bq;

    const int tid  = threadIdx.x;        // 0..511
    const int row0 = blk * 64;

    for (int i = tid; i < DKD * DKD; i += 512)
        Ws[i >> 6][i & 63] = W[i];
    for (int i = tid; i < 64 * DKD; i += 512)
        xs[i >> 6][i & 63] = x[row0 * DKD + i];
    __syncthreads();

    const int e  = tid & 63;
    const int rg = tid >> 6;             // 0..7 -> rows rg*8 .. rg*8+7
    const float b = bi[e];

    float acc[8];
#pragma unroll
    for (int j = 0; j < 8; j++) acc[j] = 0.f;

#pragma unroll
    for (int d = 0; d < DKD; d++) {
        const float w = Ws[e][d];
#pragma unroll
        for (int j = 0; j < 8; j++)
            acc[j] += w * xs[rg * 8 + j][d];
    }

    if (!is_k) {
#pragma unroll
        for (int j = 0; j < 8; j++)
            g_qp[(row0 + rg * 8 + j) * DKD + e] = acc[j] + b;   // coalesced
    } else {
        const int bh = row0 >> 8;
        const int k0 = (row0 & 255) + rg * 8;     // multiple of 8
        uint4 pk;
        pk.x = pack2(acc[0] + b, acc[1] + b);
        pk.y = pack2(acc[2] + b, acc[3] + b);
        pk.z = pack2(acc[4] + b, acc[5] + b);
        pk.w = pack2(acc[6] + b, acc[7] + b);
        *(uint4*)(g_kph + bh * (DKD * (LK / 2)) + e * (LK / 2) + (k0 >> 1)) = pk;
    }
}

// ---------------------------------------------------------------------------
// Kernel 2 (fused): scores + softmax -> attn AND output = attn @ v.
// Grid: 1024 CTAs (32 bh x 32 q-tiles). Block: 128 threads (4 warps).
// Phase 1: f16x2 path. Warp = 2 q rows; lane owns k-pairs {lane, lane+32}
//   within a 128-k chunk (2 chunks). Per d: HADD2 -> MUFU.TANH.f16x2 ->
//   HFMA2 (f16x2 accum over 8-d groups, flushed to fp32).
// Phase 2: fp32, unchanged. vs_b dropped (softmax shift-invariant).
// ---------------------------------------------------------------------------
__global__ void __launch_bounds__(128, 7)
attn_fused_kernel(const float* __restrict__ vs_w,
                  const float* __restrict__ v,
                  float* __restrict__ out,
                  float* __restrict__ attn_out)
{
    __shared__ float kv[64 * VSTRIDE];     // phase2 v chunks; aliased by kph (16KB<=16.9KB)
    __shared__ uint32_t qh2[DKD * 8];      // [d][qr] dup f16x2
    __shared__ uint32_t vswh2[DKD];        // [d] dup f16x2
    __shared__ float p_s[8 * PSTRIDE];     // [qr][k] padded

    uint32_t* kph = (uint32_t*)kv;         // phase1: [d][64 pairs] u32

    const int tid  = threadIdx.x;          // 0..127
    const int lane = tid & 31;
    const int warp = tid >> 5;             // 0..3
    const int bh   = blockIdx.x >> 5;
    const int q0   = (blockIdx.x & 31) * 8;

    if (tid < DKD) vswh2[tid] = dup2(vs_w[tid]);
    {   // build qh2[d][qr] duplicated halves from g_qp
        const int qr = tid & 7;
        const int d4 = tid >> 3;           // 0..15
        const float4 qv = *(const float4*)(g_qp + (bh * LQ + q0 + qr) * DKD + d4 * 4);
        qh2[(d4 * 4 + 0) * 8 + qr] = dup2(qv.x);
        qh2[(d4 * 4 + 1) * 8 + qr] = dup2(qv.y);
        qh2[(d4 * 4 + 2) * 8 + qr] = dup2(qv.z);
        qh2[(d4 * 4 + 3) * 8 + qr] = dup2(qv.w);
    }
    __syncthreads();

    float sc[2][8];
#pragma unroll
    for (int j = 0; j < 2; j++)
#pragma unroll
        for (int i = 0; i < 8; i++) sc[j][i] = 0.f;

    const int qw = warp * 2;

    // ---- Phase 1: scores ----
    for (int c = 0; c < 2; c++) {          // k chunks of 128 (= 64 pairs)
        if (c) __syncthreads();
        {   // stage g_kph chunk -> kph[d][pair]  (raw uint4 copy)
            const uint4* src = (const uint4*)(g_kph + bh * (DKD * (LK / 2)));
            uint4* dst = (uint4*)kph;
#pragma unroll
            for (int t = 0; t < 8; t++) {
                const int f4 = tid + t * 128;        // 0..1023
                const int d  = f4 >> 4;
                const int p4 = f4 & 15;
                dst[f4] = src[d * 32 + c * 16 + p4];
            }
        }
        __syncthreads();

#pragma unroll
        for (int d8 = 0; d8 < 8; d8++) {   // 8-d groups: f16x2 accumulate, then flush
            uint32_t a00 = 0u, a01 = 0u, a10 = 0u, a11 = 0u;
#pragma unroll
            for (int dd = 0; dd < 8; dd++) {
                const int d = d8 * 8 + dd;
                const uint32_t kp0 = kph[d * 64 + lane];
                const uint32_t kp1 = kph[d * 64 + 32 + lane];
                const uint32_t q20 = qh2[d * 8 + qw];
                const uint32_t q21 = qh2[d * 8 + qw + 1];
                const uint32_t w2  = vswh2[d];
                a00 = hfma2u(w2, tanh2(hadd2u(q20, kp0)), a00);
                a01 = hfma2u(w2, tanh2(hadd2u(q20, kp1)), a01);
                a10 = hfma2u(w2, tanh2(hadd2u(q21, kp0)), a10);
                a11 = hfma2u(w2, tanh2(hadd2u(q21, kp1)), a11);
            }
            float2 f;
            f = unpack2(a00); sc[0][c*4+0] += f.x; sc[0][c*4+1] += f.y;
            f = unpack2(a01); sc[0][c*4+2] += f.x; sc[0][c*4+3] += f.y;
            f = unpack2(a10); sc[1][c*4+0] += f.x; sc[1][c*4+1] += f.y;
            f = unpack2(a11); sc[1][c*4+2] += f.x; sc[1][c*4+3] += f.y;
        }
    }
    // lane's k for sc[j][c*4 + pi*2 + h] = c*128 + pi*64 + lane*2 + h

    // ---- softmax per q row ----
#pragma unroll
    for (int j = 0; j < 2; j++) {
        float m = sc[j][0];
#pragma unroll
        for (int i = 1; i < 8; i++) m = fmaxf(m, sc[j][i]);
#pragma unroll
        for (int o = 16; o > 0; o >>= 1)
            m = fmaxf(m, __shfl_xor_sync(0xffffffffu, m, o));

        float p[8];
        float s = 0.f;
#pragma unroll
        for (int i = 0; i < 8; i++) { p[i] = __expf(sc[j][i] - m); s += p[i]; }
#pragma unroll
        for (int o = 16; o > 0; o >>= 1)
            s += __shfl_xor_sync(0xffffffffu, s, o);

        const float inv = 1.0f / s;
        const int qr = qw + j;
        float* dst = attn_out + (bh * LQ + q0 + qr) * LK;
#pragma unroll
        for (int c = 0; c < 2; c++)
#pragma unroll
            for (int pi = 0; pi < 2; pi++) {
                const float2 pv = make_float2(p[c*4+pi*2] * inv, p[c*4+pi*2+1] * inv);
                const int kb = c * 128 + pi * 64 + lane * 2;
                *(float2*)&dst[kb]                 = pv;
                *(float2*)&p_s[qr * PSTRIDE + kb]  = pv;
            }
    }
    __syncthreads();

    // ---- Phase 2: out[q][d] = sum_k p[q][k] * v[k][d]  (fp32) ----
    const int q  = tid & 7;
    const int dg = tid >> 3;               // 0..15 -> d = dg*4 .. dg*4+3

    float acc[4];
#pragma unroll
    for (int i = 0; i < 4; i++) acc[i] = 0.f;

    for (int c = 0; c < 4; c++) {          // v chunks of 64 k-rows
        if (c) __syncthreads();
        {
            const float2* src = (const float2*)(v + (bh * LK + c * 64) * DKD);
#pragma unroll
            for (int t = 0; t < 16; t++) {
                const int f  = tid + t * 128;
                const int k  = f >> 5;
                const int d2 = f & 31;
                *(float2*)&kv[k * VSTRIDE + 2 * d2] = src[f];
            }
        }
        __syncthreads();

#pragma unroll 4
        for (int kk = 0; kk < 64; kk++) {
            const float a   = p_s[q * PSTRIDE + c * 64 + kk];
            const float2 v0 = *(const float2*)&kv[kk * VSTRIDE + dg * 4];
            const float2 v1 = *(const float2*)&kv[kk * VSTRIDE + dg * 4 + 2];
            acc[0] += a * v0.x; acc[1] += a * v0.y;
            acc[2] += a * v1.x; acc[3] += a * v1.y;
        }
    }

    float* od = out + (bh * LQ + q0 + q) * DKD + dg * 4;
    *(float4*)od = make_float4(acc[0], acc[1], acc[2], acc[3]);
}

// ---------------------------------------------------------------------------
extern "C" void kernel_launch(void* const* d_in, const int* in_sizes, int n_in,
                              void* d_out, int out_size)
{
    (void)in_sizes; (void)n_in; (void)out_size;
    const float* q    = (const float*)d_in[0];
    const float* k    = (const float*)d_in[1];
    const float* v    = (const float*)d_in[2];
    const float* Wq_w = (const float*)d_in[3];
    const float* Wq_b = (const float*)d_in[4];
    const float* Wk_w = (const float*)d_in[5];
    const float* Wk_b = (const float*)d_in[6];
    const float* vs_w = (const float*)d_in[7];
    // d_in[8] = vs_b: unused (softmax shift-invariance; scores not an output)

    float* out  = (float*)d_out;            // [B,H,Lq,Dk]
    float* attn = out + OUT_ELEMS;          // [B,H,Lq,Lk]

    proj_kernel<<<256, 512>>>(q, k, Wq_w, Wq_b, Wk_w, Wk_b);
    attn_fused_kernel<<<BHN * (LQ / 8), 128>>>(vs_w, v, out, attn);
}